// round 16
// baseline (speedup 1.0000x reference)
#include <cuda_runtime.h>
#include <math.h>
#include <cfloat>

#define N1V   384
#define NTOT  768
#define NE    3072
#define MAXD  128
#define NR    12          // columns per lane = 384/32
#define JINF  0x7fffffff
#define NPHASES 6
#define TAIL_MID  48      // phases 0..4: stop when this few rows remain free
#define TAIL_LAST 64      // final phase: SAP finisher absorbs the rest
#define QCAP  1024
#define QMASK 1023
#define BIDCAP 30000      // per-phase bid budget (livelock guard)

// ---------------- device scratch ----------------
__device__ float g_deg[NTOT];
__device__ float g_dinv[NTOT];
__device__ float g_h[2][N1V * MAXD];
__device__ float g_y[2][N1V * MAXD];
__device__ float g_x[2][N1V * MAXD];
__device__ float g_feat[2][3][N1V * MAXD];
__device__ float g_dd[2][3][N1V];
__device__ float g_Cred[3][N1V * N1V];
__device__ float g_loss[3];

// ---------------- graph normalization ----------------
__global__ void zero_deg_kernel() {
    int i = blockIdx.x * blockDim.x + threadIdx.x;
    if (i < NTOT) g_deg[i] = 0.f;
}

__global__ void deg_count_kernel(const int* __restrict__ e1, const int* __restrict__ e2) {
    int i = blockIdx.x * blockDim.x + threadIdx.x;
    if (i < NE) {
        atomicAdd(&g_deg[e1[NE + i]], 1.f);
    } else if (i < 2 * NE) {
        atomicAdd(&g_deg[N1V + e2[NE + (i - NE)]], 1.f);
    }
}

__global__ void dinv_kernel() {
    int i = blockIdx.x * blockDim.x + threadIdx.x;
    if (i < NTOT) {
        float d = g_deg[i] + 1.f;
        g_dinv[i] = 1.f / sqrtf(d);
    }
}

// ---------------- GCN layer pieces ----------------
__global__ void matmul_kernel(const float* __restrict__ Xin, const float* __restrict__ W,
                              int g, int in_dim, int out_dim) {
    __shared__ float xs[MAXD];
    int r = blockIdx.x;
    const float* X = Xin ? Xin : g_x[g];
    for (int k = threadIdx.x; k < in_dim; k += blockDim.x) xs[k] = X[r * in_dim + k];
    __syncthreads();
    int o = threadIdx.x;
    if (o < out_dim) {
        float a = 0.f;
        #pragma unroll 4
        for (int k = 0; k < in_dim; k++) a = fmaf(xs[k], W[k * out_dim + o], a);
        g_h[g][r * out_dim + o] = a;
        g_y[g][r * out_dim + o] = 0.f;
    }
}

__global__ void scatter_kernel(const int* __restrict__ ei, int g, int out_dim) {
    int idx = blockIdx.x * blockDim.x + threadIdx.x;
    int tot = (NE + N1V) * out_dim;
    if (idx >= tot) return;
    int e = idx / out_dim, f = idx - e * out_dim;
    int s, d;
    if (e < NE) { s = ei[e]; d = ei[NE + e]; }
    else        { s = d = e - NE; }
    float nm = g_dinv[g * N1V + s] * g_dinv[g * N1V + d];
    atomicAdd(&g_y[g][d * out_dim + f], nm * g_h[g][s * out_dim + f]);
}

__global__ void bias_act_kernel(const float* __restrict__ b, int g, int l, int out_dim, int dorelu) {
    int idx = blockIdx.x * blockDim.x + threadIdx.x;
    if (idx < N1V * out_dim) {
        int f = idx % out_dim;
        float v = g_y[g][idx] + b[f];
        g_feat[g][l][idx] = v;
        if (dorelu) g_x[g][idx] = fmaxf(v, 0.f);
    }
}

// ---------------- diag vectors ----------------
__global__ void dd_kernel(const float* d1, const float* d2, const float* d3,
                          const float* i1, const float* i2, const float* i3) {
    int idx = blockIdx.x * blockDim.x + threadIdx.x;
    if (idx >= 2 * 3 * N1V) return;
    int i = idx % N1V;
    int gl = idx / N1V;
    int g = gl / 3, l = gl % 3;
    const int dims[3] = {128, 64, 32};
    const float* p = (g == 0) ? ((l == 0) ? d1 : (l == 1) ? d2 : d3)
                              : ((l == 0) ? i1 : (l == 1) ? i2 : i3);
    int dk = dims[l];
    const float* f = g_feat[g][l];
    float a = 0.f;
    for (int k = 0; k < dk; k++) a = fmaf(f[i * dk + k], p[k], a);
    g_dd[g][l][i] = -a;
}

// ---------------- reduced cost: C'[i][j] = min(-(f1_i.f2_j), D[i]+I[j]) ----------------
__global__ void cost_red_kernel(int l, int dk) {
    int j = blockIdx.x * blockDim.x + threadIdx.x;
    int i = blockIdx.y;
    if (j >= N1V) return;
    const float* __restrict__ f1 = g_feat[0][l];
    const float* __restrict__ f2 = g_feat[1][l];
    float a = 0.f;
    #pragma unroll 4
    for (int k = 0; k < dk; k++) a = fmaf(f1[i * dk + k], f2[j * dk + k], a);
    float m = -a;
    float alt = g_dd[0][l][i] + g_dd[1][l][j];
    g_Cred[l][i * N1V + j] = fminf(m, alt);
}

// ---------------- ordered float <-> uint monotone map ----------------
__device__ __forceinline__ unsigned f2key(float f) {
    unsigned b = __float_as_uint(f);
    return (b & 0x80000000u) ? ~b : (b | 0x80000000u);
}
__device__ __forceinline__ float key2f(unsigned k) {
    unsigned b = (k & 0x80000000u) ? (k & 0x7fffffffu) : ~k;
    return __uint_as_float(b);
}
__device__ __forceinline__ bool lessvi(float a, int ai, float b, int bi) {
    return (a < b) || (a == b && ai < bi);
}
// lane column map: q in [0,12): j = 128*(q>>2) + 4*lane + (q&3)
__device__ __forceinline__ int q2j(int q, int lane) { return 128 * (q >> 2) + 4 * lane + (q & 3); }

// warp-cooperative two-smallest of C[i][:] + p[:] (float prices in shared)
__device__ __forceinline__ void row_two_min(const float* __restrict__ Crow,
                                            const float* __restrict__ p, int lane,
                                            float& m1, int& j1, float& m2, int& j2) {
    const float4* row = (const float4*)Crow + lane;
    const float4* pp  = (const float4*)p + lane;
    m1 = FLT_MAX; m2 = FLT_MAX; j1 = JINF; j2 = JINF;
    #pragma unroll
    for (int b = 0; b < 3; b++) {
        float4 cv = __ldg(row + 32 * b);
        float4 pv = pp[32 * b];
        float dr[4] = {cv.x + pv.x, cv.y + pv.y, cv.z + pv.z, cv.w + pv.w};
        #pragma unroll
        for (int r = 0; r < 4; r++) {
            int j = 128 * b + 4 * lane + r;
            if (lessvi(dr[r], j, m1, j1)) { m2 = m1; j2 = j1; m1 = dr[r]; j1 = j; }
            else if (lessvi(dr[r], j, m2, j2)) { m2 = dr[r]; j2 = j; }
        }
    }
    #pragma unroll
    for (int off = 16; off > 0; off >>= 1) {
        float o1 = __shfl_xor_sync(0xffffffffu, m1, off);
        int  oj1 = __shfl_xor_sync(0xffffffffu, j1, off);
        float o2 = __shfl_xor_sync(0xffffffffu, m2, off);
        int  oj2 = __shfl_xor_sync(0xffffffffu, j2, off);
        if (lessvi(o1, oj1, m1, j1)) {
            if (lessvi(m1, j1, o2, oj2)) { m2 = m1; j2 = j1; }
            else                         { m2 = o2; j2 = oj2; }
            m1 = o1; j1 = oj1;
        } else {
            if (lessvi(o1, oj1, m2, j2)) { m2 = o1; j2 = oj1; }
        }
    }
}

// ---------------- LAP: async Gauss-Seidel auction warm start + exact JV SAP --------
__global__ void __launch_bounds__(1024, 1) lap_kernel() {
    const int k = blockIdx.x;
    const float* __restrict__ C = g_Cred[k];
    const int tid  = threadIdx.x;
    const int warp = tid >> 5;
    const int lane = tid & 31;

    __shared__ __align__(16) float s_p[N1V];
    __shared__ float u[N1V], s_v[N1V], s_sh[N1V];
    __shared__ int s_path[N1V], row4col[N1V], col4row[N1V], srlist[N1V];
    __shared__ int fa[N1V + 8];
    __shared__ int cand[N1V], claim[N1V];
    __shared__ unsigned long long pw[N1V];     // packed (price_key<<32)|(owner+1)
    __shared__ int q[QCAP];                    // work queue of free rows
    __shared__ int qhead, qtail, nAssigned, bidCount;
    __shared__ unsigned sKmin, sKmax;

    // ---- 0. range of C for eps scale ----
    if (tid == 0) { sKmin = 0xFFFFFFFFu; sKmax = 0u; }
    __syncthreads();
    {
        unsigned kmin = 0xFFFFFFFFu, kmax = 0u;
        for (int t = tid; t < N1V * N1V; t += 1024) {
            unsigned key = f2key(__ldg(C + t));
            kmin = min(kmin, key); kmax = max(kmax, key);
        }
        kmin = __reduce_min_sync(0xffffffffu, kmin);
        kmax = __reduce_max_sync(0xffffffffu, kmax);
        if (lane == 0) { atomicMin(&sKmin, kmin); atomicMax(&sKmax, kmax); }
    }
    for (int j = tid; j < N1V; j += 1024)
        pw[j] = ((unsigned long long)f2key(0.f) << 32);   // price 0, no owner
    __syncthreads();
    float range = key2f(sKmax) - key2f(sKmin);
    if (!(range > 0.f)) range = 1.f;

    // ---- 1. async eps-scaling auction (no barriers in the hot loop) ----
    float eps = range * 0.25f;
    for (int phase = 0; phase < NPHASES; phase++) {
        const int target = N1V - ((phase == NPHASES - 1) ? TAIL_LAST : TAIL_MID);
        // reinit: clear owners (keep prices), refill queue with all rows
        for (int t = tid; t < N1V; t += 1024) {
            pw[t] &= 0xffffffff00000000ull;
            q[t] = t;
        }
        for (int t = N1V + tid; t < QCAP; t += 1024) q[t] = -1;
        if (tid == 0) { qhead = 0; qtail = N1V; nAssigned = 0; bidCount = 0; }
        __syncthreads();

        while (true) {
            int row = -1;
            if (lane == 0) {
                if (atomicAdd(&nAssigned, 0) >= target ||
                    atomicAdd(&bidCount, 0) >= BIDCAP) {
                    row = -2;
                } else {
                    int t = atomicAdd(&qhead, 1);
                    while (true) {
                        int r = atomicAdd(&q[t & QMASK], 0);
                        if (r >= 0) {
                            atomicExch(&q[t & QMASK], -1);
                            row = r;
                            break;
                        }
                        if (atomicAdd(&nAssigned, 0) >= target ||
                            atomicAdd(&bidCount, 0) >= BIDCAP) { row = -2; break; }
                        __nanosleep(64);
                    }
                }
            }
            row = __shfl_sync(0xffffffffu, row, 0);
            if (row < 0) break;

            // scan C[row] + current prices (snapshot per column), track raw cost at argmin
            const float4* crow = (const float4*)(C + row * N1V) + lane;
            float m1 = FLT_MAX, m2 = FLT_MAX, c1 = 0.f;
            int j1 = JINF, j2 = JINF;
            #pragma unroll
            for (int b = 0; b < 3; b++) {
                float4 cv = __ldg(crow + 32 * b);
                float cr[4] = {cv.x, cv.y, cv.z, cv.w};
                #pragma unroll
                for (int r = 0; r < 4; r++) {
                    int j = 128 * b + 4 * lane + r;
                    float price = key2f((unsigned)(pw[j] >> 32));
                    float d = cr[r] + price;
                    if (lessvi(d, j, m1, j1)) { m2 = m1; j2 = j1; m1 = d; j1 = j; c1 = cr[r]; }
                    else if (lessvi(d, j, m2, j2)) { m2 = d; j2 = j; }
                }
            }
            #pragma unroll
            for (int off = 16; off > 0; off >>= 1) {
                float o1 = __shfl_xor_sync(0xffffffffu, m1, off);
                int  oj1 = __shfl_xor_sync(0xffffffffu, j1, off);
                float oc1 = __shfl_xor_sync(0xffffffffu, c1, off);
                float o2 = __shfl_xor_sync(0xffffffffu, m2, off);
                int  oj2 = __shfl_xor_sync(0xffffffffu, j2, off);
                if (lessvi(o1, oj1, m1, j1)) {
                    if (lessvi(m1, j1, o2, oj2)) { m2 = m1; j2 = j1; }
                    else                         { m2 = o2; j2 = oj2; }
                    m1 = o1; j1 = oj1; c1 = oc1;
                } else {
                    if (lessvi(o1, oj1, m2, j2)) { m2 = o1; j2 = oj1; }
                }
            }

            if (lane == 0) {
                // new price so column j1's reduced value becomes m2 + eps
                float bid = m2 - c1 + eps;
                unsigned long long np =
                    ((unsigned long long)f2key(bid) << 32) | (unsigned)(row + 1);
                unsigned long long old = atomicMax(&pw[j1], np);
                if (old < np) {                       // won
                    int oo = (int)(old & 0xffffffffu);
                    if (oo == 0) {
                        atomicAdd(&nAssigned, 1);
                    } else {
                        int slot = atomicAdd(&qtail, 1) & QMASK;
                        atomicExch(&q[slot], oo - 1);
                    }
                } else {                              // lost: retry later
                    int slot = atomicAdd(&qtail, 1) & QMASK;
                    atomicExch(&q[slot], row);
                }
                atomicAdd(&bidCount, 1);
            }
            __syncwarp();
        }
        __syncthreads();
        eps *= 0.125f;
    }

    // extract float prices for the exact phase
    for (int j = tid; j < N1V; j += 1024) {
        s_p[j] = key2f((unsigned)(pw[j] >> 32));
        s_v[j] = -s_p[j];
        claim[j] = JINF;
        row4col[j] = -1;
    }
    __syncthreads();

    // ---- 2. exact duals: u[i]=min_j(C[i,j]+p[j]), v=-p; claim tight argmins ----
    for (int i = warp; i < N1V; i += 32) {
        float m1, m2; int j1, j2;
        row_two_min(C + i * N1V, s_p, lane, m1, j1, m2, j2);
        if (lane == 0) { u[i] = m1; cand[i] = j1; }
    }
    __syncthreads();
    for (int i = tid; i < N1V; i += 1024) atomicMin(&claim[cand[i]], i);
    __syncthreads();
    for (int i = tid; i < N1V; i += 1024) {
        int j = cand[i];
        if (claim[j] == i) { col4row[i] = j; row4col[j] = i; }
        else               col4row[i] = -1;
    }
    __syncthreads();

    // ---- 3. exact JV shortest-augmenting-path on warp 0 ----
    if (warp == 0) {
        int nfree = 0;
        if (lane == 0) {
            for (int i = 0; i < N1V; i++)
                if (col4row[i] < 0) fa[nfree++] = i;
        }
        nfree = __shfl_sync(0xffffffffu, nfree, 0);

        float v[NR];
        #pragma unroll
        for (int qq = 0; qq < NR; qq++) v[qq] = s_v[q2j(qq, lane)];
        __syncwarp();

        for (int f = 0; f < nfree; f++) {
            int cur = fa[f];

            float sh[NR]; int pathq[NR];
            #pragma unroll
            for (int qq = 0; qq < NR; qq++) { sh[qq] = FLT_MAX; pathq[qq] = -1; }
            unsigned scq = 0;
            int i = cur, srcount = 0, sink = -1;
            float minval = 0.f;

            while (sink < 0) {
                if (lane == 0) srlist[srcount] = i;
                srcount++;

                const float4* crow = (const float4*)(C + i * N1V) + lane;
                float4 c0 = __ldg(crow), c1v = __ldg(crow + 32), c2v = __ldg(crow + 64);
                float c[NR] = {c0.x, c0.y, c0.z, c0.w, c1v.x, c1v.y, c1v.z, c1v.w,
                               c2v.x, c2v.y, c2v.z, c2v.w};

                float base = minval - u[i];
                float dv[NR];
                #pragma unroll
                for (int qq = 0; qq < NR; qq++) {
                    float sj = sh[qq];
                    if (!((scq >> qq) & 1u)) {
                        float d = base + c[qq] - v[qq];
                        if (d < sj) { sj = d; sh[qq] = d; pathq[qq] = i; }
                        dv[qq] = sj;
                    } else {
                        dv[qq] = FLT_MAX;
                    }
                }

                float m6[6]; int j6[6];
                #pragma unroll
                for (int t = 0; t < 6; t++) {
                    int qa = 2 * t, qb = 2 * t + 1;
                    if (dv[qa] <= dv[qb]) { m6[t] = dv[qa]; j6[t] = q2j(qa, lane); }
                    else                  { m6[t] = dv[qb]; j6[t] = q2j(qb, lane); }
                }
                float m3[3]; int j3[3];
                #pragma unroll
                for (int t = 0; t < 3; t++) {
                    if (m6[2 * t] <= m6[2 * t + 1]) { m3[t] = m6[2 * t]; j3[t] = j6[2 * t]; }
                    else                            { m3[t] = m6[2 * t + 1]; j3[t] = j6[2 * t + 1]; }
                }
                float bv; int bj;
                if (m3[0] <= m3[1]) { bv = m3[0]; bj = j3[0]; } else { bv = m3[1]; bj = j3[1]; }
                if (m3[2] < bv)     { bv = m3[2]; bj = j3[2]; }

                unsigned key = f2key(bv);
                unsigned mk  = __reduce_min_sync(0xffffffffu, key);
                unsigned ball = __ballot_sync(0xffffffffu, key == mk);
                int src = __ffs(ball) - 1;
                int bestj = __shfl_sync(0xffffffffu, bj, src);
                minval = key2f(mk);

                if (((bestj >> 2) & 31) == lane) scq |= 1u << (((bestj >> 7) << 2) | (bestj & 3));
                int rc = row4col[bestj];
                if (rc < 0) sink = bestj;
                else        i = rc;
            }

            #pragma unroll
            for (int qq = 0; qq < NR; qq++) {
                int j = q2j(qq, lane);
                s_sh[j] = sh[qq];
                s_path[j] = pathq[qq];
            }
            __syncwarp();

            for (int s = lane; s < srcount; s += 32) {
                int r = srlist[s];
                if (r == cur) u[r] += minval;
                else          u[r] += minval - s_sh[col4row[r]];
            }
            #pragma unroll
            for (int qq = 0; qq < NR; qq++)
                if ((scq >> qq) & 1u) v[qq] -= minval - sh[qq];
            __syncwarp();

            if (lane == 0) {
                int j = sink;
                while (true) {
                    int i2 = s_path[j];
                    row4col[j] = i2;
                    int tmp = col4row[i2];
                    col4row[i2] = j;
                    j = tmp;
                    if (i2 == cur) break;
                }
            }
            __syncwarp();
        }

        // optimal value / 768
        double acc = 0.0;
        for (int r = lane; r < N1V; r += 32)
            acc += (double)C[r * N1V + col4row[r]];
        #pragma unroll
        for (int off = 16; off > 0; off >>= 1)
            acc += __shfl_down_sync(0xffffffffu, acc, off);
        if (lane == 0) g_loss[k] = (float)(acc / (double)NTOT);
    }
    __syncthreads();
}

// ---------------- scalar head ----------------
__global__ void final_kernel(const float* __restrict__ sw, const float* __restrict__ sb,
                             const float* __restrict__ avg, float* __restrict__ out) {
    float mc[3];
    #pragma unroll
    for (int k = 0; k < 3; k++) mc[k] = 2.f * g_loss[k] / (float)NTOT;
    float logit = sb[0];
    #pragma unroll
    for (int k = 0; k < 3; k++) logit += sw[k] * mc[k];
    float score = 1.f / (1.f + expf(-logit));
    out[0] = score;
    out[1] = -logf(score) * avg[0];
    out[2] = mc[0];
    out[3] = mc[1];
    out[4] = mc[2];
}

// ---------------- host launcher ----------------
extern "C" void kernel_launch(void* const* d_in, const int* in_sizes, int n_in,
                              void* d_out, int out_size) {
    int base;
    if (n_in >= 21) base = 6;
    else            base = 4;
    const int ws = base + 1;
    const bool sigOrder = (in_sizes[ws + 2] == 8192);

    int iW[3], iB[3], iDel[3], iIns[3], iSW, iSB;
    if (sigOrder) {
        for (int l = 0; l < 3; l++) { iW[l] = ws + 2 * l; iB[l] = ws + 2 * l + 1; }
        for (int l = 0; l < 3; l++) { iDel[l] = ws + 6 + l; iIns[l] = ws + 9 + l; }
        iSW = ws + 12; iSB = ws + 13;
    } else {
        for (int l = 0; l < 3; l++) {
            iW[l] = ws + 4 * l; iB[l] = ws + 4 * l + 1;
            iDel[l] = ws + 4 * l + 2; iIns[l] = ws + 4 * l + 3;
        }
        iSW = ws + 12; iSB = ws + 13;
    }

    const int*   e1  = (const int*)d_in[0];
    const int*   e2  = (const int*)d_in[1];
    const float* f1  = (const float*)d_in[2];
    const float* f2  = (const float*)d_in[3];
    const float* avg = (const float*)d_in[base];
    float* out = (float*)d_out;
    (void)out_size;

    zero_deg_kernel<<<3, 256>>>();
    deg_count_kernel<<<(2 * NE + 255) / 256, 256>>>(e1, e2);
    dinv_kernel<<<3, 256>>>();

    const int in_dims[3]  = {32, 128, 64};
    const int out_dims[3] = {128, 64, 32};

    for (int g = 0; g < 2; g++) {
        const float* x0 = (g == 0) ? f1 : f2;
        const int* ei = (g == 0) ? e1 : e2;
        for (int l = 0; l < 3; l++) {
            const float* W = (const float*)d_in[iW[l]];
            const float* B = (const float*)d_in[iB[l]];
            const float* Xin = (l == 0) ? x0 : nullptr;
            int in_d = in_dims[l], out_d = out_dims[l];
            matmul_kernel<<<N1V, out_d>>>(Xin, W, g, in_d, out_d);
            int cnt = N1V * out_d;
            int tot = (NE + N1V) * out_d;
            scatter_kernel<<<(tot + 255) / 256, 256>>>(ei, g, out_d);
            bias_act_kernel<<<(cnt + 255) / 256, 256>>>(B, g, l, out_d, (l < 2) ? 1 : 0);
        }
    }

    dd_kernel<<<9, 256>>>((const float*)d_in[iDel[0]], (const float*)d_in[iDel[1]],
                          (const float*)d_in[iDel[2]], (const float*)d_in[iIns[0]],
                          (const float*)d_in[iIns[1]], (const float*)d_in[iIns[2]]);

    for (int l = 0; l < 3; l++) {
        dim3 grid((N1V + 127) / 128, N1V);
        cost_red_kernel<<<grid, 128>>>(l, out_dims[l]);
    }

    lap_kernel<<<3, 1024>>>();

    final_kernel<<<1, 1>>>((const float*)d_in[iSW], (const float*)d_in[iSB], avg, out);
}

// round 17
// speedup vs baseline: 1.8479x; 1.8479x over previous
#include <cuda_runtime.h>
#include <math.h>
#include <cfloat>

#define N1V   384
#define NTOT  768
#define NE    3072
#define MAXD  128
#define NR    12          // columns per lane = 384/32
#define JINF  0x7fffffff
#define NPHASES 6
#define TAIL_MID  24      // phases 0..4: stop when this few rows remain free
#define TAIL_LAST 64      // final phase: SAP finisher absorbs the rest
#define QCAP  1024
#define QMASK 1023
#define BIDCAP 30000      // per-phase bid budget (livelock guard)

// ---------------- device scratch ----------------
__device__ float g_deg[NTOT];
__device__ float g_dinv[NTOT];
__device__ float g_h[2][N1V * MAXD];
__device__ float g_y[2][N1V * MAXD];
__device__ float g_x[2][N1V * MAXD];
__device__ float g_feat[2][3][N1V * MAXD];
__device__ float g_dd[2][3][N1V];
__device__ float g_Cred[3][N1V * N1V];
__device__ float g_loss[3];

// ---------------- graph normalization ----------------
__global__ void zero_deg_kernel() {
    int i = blockIdx.x * blockDim.x + threadIdx.x;
    if (i < NTOT) g_deg[i] = 0.f;
}

__global__ void deg_count_kernel(const int* __restrict__ e1, const int* __restrict__ e2) {
    int i = blockIdx.x * blockDim.x + threadIdx.x;
    if (i < NE) {
        atomicAdd(&g_deg[e1[NE + i]], 1.f);
    } else if (i < 2 * NE) {
        atomicAdd(&g_deg[N1V + e2[NE + (i - NE)]], 1.f);
    }
}

__global__ void dinv_kernel() {
    int i = blockIdx.x * blockDim.x + threadIdx.x;
    if (i < NTOT) {
        float d = g_deg[i] + 1.f;
        g_dinv[i] = 1.f / sqrtf(d);
    }
}

// ---------------- GCN layer pieces ----------------
__global__ void matmul_kernel(const float* __restrict__ Xin, const float* __restrict__ W,
                              int g, int in_dim, int out_dim) {
    __shared__ float xs[MAXD];
    int r = blockIdx.x;
    const float* X = Xin ? Xin : g_x[g];
    for (int k = threadIdx.x; k < in_dim; k += blockDim.x) xs[k] = X[r * in_dim + k];
    __syncthreads();
    int o = threadIdx.x;
    if (o < out_dim) {
        float a = 0.f;
        #pragma unroll 4
        for (int k = 0; k < in_dim; k++) a = fmaf(xs[k], W[k * out_dim + o], a);
        g_h[g][r * out_dim + o] = a;
        g_y[g][r * out_dim + o] = 0.f;
    }
}

__global__ void scatter_kernel(const int* __restrict__ ei, int g, int out_dim) {
    int idx = blockIdx.x * blockDim.x + threadIdx.x;
    int tot = (NE + N1V) * out_dim;
    if (idx >= tot) return;
    int e = idx / out_dim, f = idx - e * out_dim;
    int s, d;
    if (e < NE) { s = ei[e]; d = ei[NE + e]; }
    else        { s = d = e - NE; }
    float nm = g_dinv[g * N1V + s] * g_dinv[g * N1V + d];
    atomicAdd(&g_y[g][d * out_dim + f], nm * g_h[g][s * out_dim + f]);
}

__global__ void bias_act_kernel(const float* __restrict__ b, int g, int l, int out_dim, int dorelu) {
    int idx = blockIdx.x * blockDim.x + threadIdx.x;
    if (idx < N1V * out_dim) {
        int f = idx % out_dim;
        float v = g_y[g][idx] + b[f];
        g_feat[g][l][idx] = v;
        if (dorelu) g_x[g][idx] = fmaxf(v, 0.f);
    }
}

// ---------------- diag vectors ----------------
__global__ void dd_kernel(const float* d1, const float* d2, const float* d3,
                          const float* i1, const float* i2, const float* i3) {
    int idx = blockIdx.x * blockDim.x + threadIdx.x;
    if (idx >= 2 * 3 * N1V) return;
    int i = idx % N1V;
    int gl = idx / N1V;
    int g = gl / 3, l = gl % 3;
    const int dims[3] = {128, 64, 32};
    const float* p = (g == 0) ? ((l == 0) ? d1 : (l == 1) ? d2 : d3)
                              : ((l == 0) ? i1 : (l == 1) ? i2 : i3);
    int dk = dims[l];
    const float* f = g_feat[g][l];
    float a = 0.f;
    for (int k = 0; k < dk; k++) a = fmaf(f[i * dk + k], p[k], a);
    g_dd[g][l][i] = -a;
}

// ---------------- reduced cost: C'[i][j] = min(-(f1_i.f2_j), D[i]+I[j]) ----------------
__global__ void cost_red_kernel(int l, int dk) {
    int j = blockIdx.x * blockDim.x + threadIdx.x;
    int i = blockIdx.y;
    if (j >= N1V) return;
    const float* __restrict__ f1 = g_feat[0][l];
    const float* __restrict__ f2 = g_feat[1][l];
    float a = 0.f;
    #pragma unroll 4
    for (int k = 0; k < dk; k++) a = fmaf(f1[i * dk + k], f2[j * dk + k], a);
    float m = -a;
    float alt = g_dd[0][l][i] + g_dd[1][l][j];
    g_Cred[l][i * N1V + j] = fminf(m, alt);
}

// ---------------- ordered float <-> uint monotone map ----------------
__device__ __forceinline__ unsigned f2key(float f) {
    unsigned b = __float_as_uint(f);
    return (b & 0x80000000u) ? ~b : (b | 0x80000000u);
}
__device__ __forceinline__ float key2f(unsigned k) {
    unsigned b = (k & 0x80000000u) ? (k & 0x7fffffffu) : ~k;
    return __uint_as_float(b);
}
__device__ __forceinline__ bool lessvi(float a, int ai, float b, int bi) {
    return (a < b) || (a == b && ai < bi);
}
// lane column map: q in [0,12): j = 128*(q>>2) + 4*lane + (q&3)
__device__ __forceinline__ int q2j(int q, int lane) { return 128 * (q >> 2) + 4 * lane + (q & 3); }

// warp-cooperative two-smallest of C[i][:] + p[:] (float prices in shared)
__device__ __forceinline__ void row_two_min(const float* __restrict__ Crow,
                                            const float* __restrict__ p, int lane,
                                            float& m1, int& j1, float& m2, int& j2) {
    const float4* row = (const float4*)Crow + lane;
    const float4* pp  = (const float4*)p + lane;
    m1 = FLT_MAX; m2 = FLT_MAX; j1 = JINF; j2 = JINF;
    #pragma unroll
    for (int b = 0; b < 3; b++) {
        float4 cv = __ldg(row + 32 * b);
        float4 pv = pp[32 * b];
        float dr[4] = {cv.x + pv.x, cv.y + pv.y, cv.z + pv.z, cv.w + pv.w};
        #pragma unroll
        for (int r = 0; r < 4; r++) {
            int j = 128 * b + 4 * lane + r;
            if (lessvi(dr[r], j, m1, j1)) { m2 = m1; j2 = j1; m1 = dr[r]; j1 = j; }
            else if (lessvi(dr[r], j, m2, j2)) { m2 = dr[r]; j2 = j; }
        }
    }
    #pragma unroll
    for (int off = 16; off > 0; off >>= 1) {
        float o1 = __shfl_xor_sync(0xffffffffu, m1, off);
        int  oj1 = __shfl_xor_sync(0xffffffffu, j1, off);
        float o2 = __shfl_xor_sync(0xffffffffu, m2, off);
        int  oj2 = __shfl_xor_sync(0xffffffffu, j2, off);
        if (lessvi(o1, oj1, m1, j1)) {
            if (lessvi(m1, j1, o2, oj2)) { m2 = m1; j2 = j1; }
            else                         { m2 = o2; j2 = oj2; }
            m1 = o1; j1 = oj1;
        } else {
            if (lessvi(o1, oj1, m2, j2)) { m2 = o1; j2 = oj1; }
        }
    }
}

// ---------------- LAP: async Gauss-Seidel auction warm start + exact JV SAP --------
__global__ void __launch_bounds__(1024, 1) lap_kernel() {
    const int k = blockIdx.x;
    const float* __restrict__ C = g_Cred[k];
    const int tid  = threadIdx.x;
    const int warp = tid >> 5;
    const int lane = tid & 31;

    __shared__ __align__(16) float s_p[N1V];
    __shared__ float u[N1V], s_v[N1V], s_sh[N1V];
    __shared__ int s_path[N1V], row4col[N1V], col4row[N1V], srlist[N1V];
    __shared__ int fa[N1V + 8];
    __shared__ int cand[N1V], claim[N1V];
    __shared__ unsigned long long pw[N1V];     // packed (price_key<<32)|(owner+1)
    __shared__ int q[QCAP];                    // work queue of free rows
    __shared__ int qhead, qtail, nAssigned, bidCount;
    __shared__ unsigned sKmin, sKmax;

    // ---- 0. range of C for eps scale ----
    if (tid == 0) { sKmin = 0xFFFFFFFFu; sKmax = 0u; }
    __syncthreads();
    {
        unsigned kmin = 0xFFFFFFFFu, kmax = 0u;
        for (int t = tid; t < N1V * N1V; t += 1024) {
            unsigned key = f2key(__ldg(C + t));
            kmin = min(kmin, key); kmax = max(kmax, key);
        }
        kmin = __reduce_min_sync(0xffffffffu, kmin);
        kmax = __reduce_max_sync(0xffffffffu, kmax);
        if (lane == 0) { atomicMin(&sKmin, kmin); atomicMax(&sKmax, kmax); }
    }
    for (int j = tid; j < N1V; j += 1024)
        pw[j] = ((unsigned long long)f2key(0.f) << 32);   // price 0, no owner
    __syncthreads();
    float range = key2f(sKmax) - key2f(sKmin);
    if (!(range > 0.f)) range = 1.f;

    // ---- 1. async eps-scaling auction with displacement-chain following ----
    float eps = range * 0.25f;
    for (int phase = 0; phase < NPHASES; phase++) {
        const int target = N1V - ((phase == NPHASES - 1) ? TAIL_LAST : TAIL_MID);
        // reinit: clear owners (keep prices), refill queue with all rows
        for (int t = tid; t < N1V; t += 1024) {
            pw[t] &= 0xffffffff00000000ull;
            q[t] = t;
        }
        for (int t = N1V + tid; t < QCAP; t += 1024) q[t] = -1;
        if (tid == 0) { qhead = 0; qtail = N1V; nAssigned = 0; bidCount = 0; }
        __syncthreads();

        int row = -1;     // current row carried across chain links (warp-uniform)
        while (true) {
            if (row < 0) {
                // pop a fresh row from the queue
                int r0 = -1;
                if (lane == 0) {
                    if (atomicAdd(&nAssigned, 0) >= target ||
                        atomicAdd(&bidCount, 0) >= BIDCAP) {
                        r0 = -2;
                    } else {
                        int t = atomicAdd(&qhead, 1);
                        while (true) {
                            int r = atomicAdd(&q[t & QMASK], 0);
                            if (r >= 0) {
                                atomicExch(&q[t & QMASK], -1);
                                r0 = r;
                                break;
                            }
                            if (atomicAdd(&nAssigned, 0) >= target ||
                                atomicAdd(&bidCount, 0) >= BIDCAP) { r0 = -2; break; }
                            __nanosleep(64);
                        }
                    }
                }
                row = __shfl_sync(0xffffffffu, r0, 0);
                if (row == -2) break;
            } else {
                // mid-chain: cheap termination check
                int stop = 0;
                if (lane == 0)
                    stop = (atomicAdd(&nAssigned, 0) >= target ||
                            atomicAdd(&bidCount, 0) >= BIDCAP) ? 1 : 0;
                if (__shfl_sync(0xffffffffu, stop, 0)) break;
            }

            // scan C[row] + current prices (snapshot per column), track raw cost at argmin
            const float4* crow = (const float4*)(C + row * N1V) + lane;
            float m1 = FLT_MAX, m2 = FLT_MAX, c1 = 0.f;
            int j1 = JINF, j2 = JINF;
            #pragma unroll
            for (int b = 0; b < 3; b++) {
                float4 cv = __ldg(crow + 32 * b);
                float cr[4] = {cv.x, cv.y, cv.z, cv.w};
                #pragma unroll
                for (int r = 0; r < 4; r++) {
                    int j = 128 * b + 4 * lane + r;
                    float price = key2f((unsigned)(pw[j] >> 32));
                    float d = cr[r] + price;
                    if (lessvi(d, j, m1, j1)) { m2 = m1; j2 = j1; m1 = d; j1 = j; c1 = cr[r]; }
                    else if (lessvi(d, j, m2, j2)) { m2 = d; j2 = j; }
                }
            }
            #pragma unroll
            for (int off = 16; off > 0; off >>= 1) {
                float o1 = __shfl_xor_sync(0xffffffffu, m1, off);
                int  oj1 = __shfl_xor_sync(0xffffffffu, j1, off);
                float oc1 = __shfl_xor_sync(0xffffffffu, c1, off);
                float o2 = __shfl_xor_sync(0xffffffffu, m2, off);
                int  oj2 = __shfl_xor_sync(0xffffffffu, j2, off);
                if (lessvi(o1, oj1, m1, j1)) {
                    if (lessvi(m1, j1, o2, oj2)) { m2 = m1; j2 = j1; }
                    else                         { m2 = o2; j2 = oj2; }
                    m1 = o1; j1 = oj1; c1 = oc1;
                } else {
                    if (lessvi(o1, oj1, m2, j2)) { m2 = o1; j2 = oj1; }
                }
            }

            int nextrow = -1;
            if (lane == 0) {
                // new price so column j1's reduced value becomes m2 + eps
                float bid = m2 - c1 + eps;
                unsigned long long np =
                    ((unsigned long long)f2key(bid) << 32) | (unsigned)(row + 1);
                unsigned long long old = atomicMax(&pw[j1], np);
                if (old < np) {                       // won
                    int oo = (int)(old & 0xffffffffu);
                    if (oo == 0) {
                        atomicAdd(&nAssigned, 1);
                        nextrow = -1;                 // chain ends: pop fresh row
                    } else {
                        nextrow = oo - 1;             // follow displacement chain
                    }
                } else {                              // lost: retry same row (prices rose)
                    nextrow = row;
                }
                atomicAdd(&bidCount, 1);
            }
            row = __shfl_sync(0xffffffffu, nextrow, 0);
        }
        __syncthreads();
        eps *= 0.125f;
    }

    // extract float prices for the exact phase
    for (int j = tid; j < N1V; j += 1024) {
        s_p[j] = key2f((unsigned)(pw[j] >> 32));
        s_v[j] = -s_p[j];
        claim[j] = JINF;
        row4col[j] = -1;
    }
    __syncthreads();

    // ---- 2. exact duals: u[i]=min_j(C[i,j]+p[j]), v=-p; claim tight argmins ----
    for (int i = warp; i < N1V; i += 32) {
        float m1, m2; int j1, j2;
        row_two_min(C + i * N1V, s_p, lane, m1, j1, m2, j2);
        if (lane == 0) { u[i] = m1; cand[i] = j1; }
    }
    __syncthreads();
    for (int i = tid; i < N1V; i += 1024) atomicMin(&claim[cand[i]], i);
    __syncthreads();
    for (int i = tid; i < N1V; i += 1024) {
        int j = cand[i];
        if (claim[j] == i) { col4row[i] = j; row4col[j] = i; }
        else               col4row[i] = -1;
    }
    __syncthreads();

    // ---- 3. exact JV shortest-augmenting-path on warp 0 ----
    if (warp == 0) {
        int nfree = 0;
        if (lane == 0) {
            for (int i = 0; i < N1V; i++)
                if (col4row[i] < 0) fa[nfree++] = i;
        }
        nfree = __shfl_sync(0xffffffffu, nfree, 0);

        float v[NR];
        #pragma unroll
        for (int qq = 0; qq < NR; qq++) v[qq] = s_v[q2j(qq, lane)];
        __syncwarp();

        for (int f = 0; f < nfree; f++) {
            int cur = fa[f];

            float sh[NR]; int pathq[NR];
            #pragma unroll
            for (int qq = 0; qq < NR; qq++) { sh[qq] = FLT_MAX; pathq[qq] = -1; }
            unsigned scq = 0;
            int i = cur, srcount = 0, sink = -1;
            float minval = 0.f;

            while (sink < 0) {
                if (lane == 0) srlist[srcount] = i;
                srcount++;

                const float4* crow = (const float4*)(C + i * N1V) + lane;
                float4 c0 = __ldg(crow), c1v = __ldg(crow + 32), c2v = __ldg(crow + 64);
                float c[NR] = {c0.x, c0.y, c0.z, c0.w, c1v.x, c1v.y, c1v.z, c1v.w,
                               c2v.x, c2v.y, c2v.z, c2v.w};

                float base = minval - u[i];
                float dv[NR];
                #pragma unroll
                for (int qq = 0; qq < NR; qq++) {
                    float sj = sh[qq];
                    if (!((scq >> qq) & 1u)) {
                        float d = base + c[qq] - v[qq];
                        if (d < sj) { sj = d; sh[qq] = d; pathq[qq] = i; }
                        dv[qq] = sj;
                    } else {
                        dv[qq] = FLT_MAX;
                    }
                }

                float m6[6]; int j6[6];
                #pragma unroll
                for (int t = 0; t < 6; t++) {
                    int qa = 2 * t, qb = 2 * t + 1;
                    if (dv[qa] <= dv[qb]) { m6[t] = dv[qa]; j6[t] = q2j(qa, lane); }
                    else                  { m6[t] = dv[qb]; j6[t] = q2j(qb, lane); }
                }
                float m3[3]; int j3[3];
                #pragma unroll
                for (int t = 0; t < 3; t++) {
                    if (m6[2 * t] <= m6[2 * t + 1]) { m3[t] = m6[2 * t]; j3[t] = j6[2 * t]; }
                    else                            { m3[t] = m6[2 * t + 1]; j3[t] = j6[2 * t + 1]; }
                }
                float bv; int bj;
                if (m3[0] <= m3[1]) { bv = m3[0]; bj = j3[0]; } else { bv = m3[1]; bj = j3[1]; }
                if (m3[2] < bv)     { bv = m3[2]; bj = j3[2]; }

                unsigned key = f2key(bv);
                unsigned mk  = __reduce_min_sync(0xffffffffu, key);
                unsigned ball = __ballot_sync(0xffffffffu, key == mk);
                int src = __ffs(ball) - 1;
                int bestj = __shfl_sync(0xffffffffu, bj, src);
                minval = key2f(mk);

                if (((bestj >> 2) & 31) == lane) scq |= 1u << (((bestj >> 7) << 2) | (bestj & 3));
                int rc = row4col[bestj];
                if (rc < 0) sink = bestj;
                else        i = rc;
            }

            #pragma unroll
            for (int qq = 0; qq < NR; qq++) {
                int j = q2j(qq, lane);
                s_sh[j] = sh[qq];
                s_path[j] = pathq[qq];
            }
            __syncwarp();

            for (int s = lane; s < srcount; s += 32) {
                int r = srlist[s];
                if (r == cur) u[r] += minval;
                else          u[r] += minval - s_sh[col4row[r]];
            }
            #pragma unroll
            for (int qq = 0; qq < NR; qq++)
                if ((scq >> qq) & 1u) v[qq] -= minval - sh[qq];
            __syncwarp();

            if (lane == 0) {
                int j = sink;
                while (true) {
                    int i2 = s_path[j];
                    row4col[j] = i2;
                    int tmp = col4row[i2];
                    col4row[i2] = j;
                    j = tmp;
                    if (i2 == cur) break;
                }
            }
            __syncwarp();
        }

        // optimal value / 768
        double acc = 0.0;
        for (int r = lane; r < N1V; r += 32)
            acc += (double)C[r * N1V + col4row[r]];
        #pragma unroll
        for (int off = 16; off > 0; off >>= 1)
            acc += __shfl_down_sync(0xffffffffu, acc, off);
        if (lane == 0) g_loss[k] = (float)(acc / (double)NTOT);
    }
    __syncthreads();
}

// ---------------- scalar head ----------------
__global__ void final_kernel(const float* __restrict__ sw, const float* __restrict__ sb,
                             const float* __restrict__ avg, float* __restrict__ out) {
    float mc[3];
    #pragma unroll
    for (int k = 0; k < 3; k++) mc[k] = 2.f * g_loss[k] / (float)NTOT;
    float logit = sb[0];
    #pragma unroll
    for (int k = 0; k < 3; k++) logit += sw[k] * mc[k];
    float score = 1.f / (1.f + expf(-logit));
    out[0] = score;
    out[1] = -logf(score) * avg[0];
    out[2] = mc[0];
    out[3] = mc[1];
    out[4] = mc[2];
}

// ---------------- host launcher ----------------
extern "C" void kernel_launch(void* const* d_in, const int* in_sizes, int n_in,
                              void* d_out, int out_size) {
    int base;
    if (n_in >= 21) base = 6;
    else            base = 4;
    const int ws = base + 1;
    const bool sigOrder = (in_sizes[ws + 2] == 8192);

    int iW[3], iB[3], iDel[3], iIns[3], iSW, iSB;
    if (sigOrder) {
        for (int l = 0; l < 3; l++) { iW[l] = ws + 2 * l; iB[l] = ws + 2 * l + 1; }
        for (int l = 0; l < 3; l++) { iDel[l] = ws + 6 + l; iIns[l] = ws + 9 + l; }
        iSW = ws + 12; iSB = ws + 13;
    } else {
        for (int l = 0; l < 3; l++) {
            iW[l] = ws + 4 * l; iB[l] = ws + 4 * l + 1;
            iDel[l] = ws + 4 * l + 2; iIns[l] = ws + 4 * l + 3;
        }
        iSW = ws + 12; iSB = ws + 13;
    }

    const int*   e1  = (const int*)d_in[0];
    const int*   e2  = (const int*)d_in[1];
    const float* f1  = (const float*)d_in[2];
    const float* f2  = (const float*)d_in[3];
    const float* avg = (const float*)d_in[base];
    float* out = (float*)d_out;
    (void)out_size;

    zero_deg_kernel<<<3, 256>>>();
    deg_count_kernel<<<(2 * NE + 255) / 256, 256>>>(e1, e2);
    dinv_kernel<<<3, 256>>>();

    const int in_dims[3]  = {32, 128, 64};
    const int out_dims[3] = {128, 64, 32};

    for (int g = 0; g < 2; g++) {
        const float* x0 = (g == 0) ? f1 : f2;
        const int* ei = (g == 0) ? e1 : e2;
        for (int l = 0; l < 3; l++) {
            const float* W = (const float*)d_in[iW[l]];
            const float* B = (const float*)d_in[iB[l]];
            const float* Xin = (l == 0) ? x0 : nullptr;
            int in_d = in_dims[l], out_d = out_dims[l];
            matmul_kernel<<<N1V, out_d>>>(Xin, W, g, in_d, out_d);
            int cnt = N1V * out_d;
            int tot = (NE + N1V) * out_d;
            scatter_kernel<<<(tot + 255) / 256, 256>>>(ei, g, out_d);
            bias_act_kernel<<<(cnt + 255) / 256, 256>>>(B, g, l, out_d, (l < 2) ? 1 : 0);
        }
    }

    dd_kernel<<<9, 256>>>((const float*)d_in[iDel[0]], (const float*)d_in[iDel[1]],
                          (const float*)d_in[iDel[2]], (const float*)d_in[iIns[0]],
                          (const float*)d_in[iIns[1]], (const float*)d_in[iIns[2]]);

    for (int l = 0; l < 3; l++) {
        dim3 grid((N1V + 127) / 128, N1V);
        cost_red_kernel<<<grid, 128>>>(l, out_dims[l]);
    }

    lap_kernel<<<3, 1024>>>();

    final_kernel<<<1, 1>>>((const float*)d_in[iSW], (const float*)d_in[iSB], avg, out);
}